// round 8
// baseline (speedup 1.0000x reference)
#include <cuda_runtime.h>
#include <cstdint>

#define HID   256
#define BATCH 512
#define TLEN  256
#define NSLOT 64
#define GB    4
#define NCTA  (BATCH / GB)
#define LN_EPS 1e-5f

// ---- device scratch (no allocations allowed) ----
__device__ float g_Wt[HID * HID];                        // W_update transposed: Wt[i*H+j] = W[j*H+i]
__device__ float g_mem[(size_t)BATCH * NSLOT * HID];     // 32 MB memory slab
__device__ float g_wtab[TLEN * 8];                       // per-step softmax weights (5 used)
__device__ int   g_itab[TLEN * 8];                       // per-step slot indices (5 used)

// Zero the memory slab every launch (graph replays must be deterministic).
__global__ void zero_mem_kernel() {
    size_t i = (size_t)blockIdx.x * blockDim.x + threadIdx.x;
    size_t n = (size_t)BATCH * NSLOT * HID / 4;
    if (i < n) ((float4*)g_mem)[i] = make_float4(0.f, 0.f, 0.f, 0.f);
}

// Transpose W_update + build the per-t gaussian-attention tables.
__global__ void prep_kernel(const float* __restrict__ Wu) {
    int i = blockIdx.x;    // input dim
    int j = threadIdx.x;   // output dim
    g_Wt[i * HID + j] = Wu[j * HID + i];
    if (i == 0) {
        int t = j;
        int base = t % NSLOT;                 // pointer is exactly t % 64 (same for all batches)
        float e[5]; int idx[5]; float s = 0.f;
        #pragma unroll
        for (int k = 0; k < 5; k++) {
            int ii = base + k - 2;
            ii = (ii % NSLOT + NSLOT) % NSLOT; // python-style mod
            idx[k] = ii;
            float d = (float)ii - (float)base; // delta = wrapped index - pointer
            e[k] = expf(-(d * d) * (1.f / 8.f));
            s += e[k];
        }
        float inv = 1.f / s;
        #pragma unroll
        for (int k = 0; k < 5; k++) {
            g_wtab[t * 8 + k] = e[k] * inv;
            g_itab[t * 8 + k] = idx[k];
        }
    }
}

// tanh via __expf: accurate to ~1e-7 rel and immune to fast-math tanhf->MUFU.TANH
// substitution (whose ~1e-3 abs error would compound over 256 recurrent steps).
__device__ __forceinline__ float fast_tanh(float z) {
    float a = fabsf(z);
    float e = __expf(-2.f * a);
    float r = (1.f - e) / (1.f + e);
    return z < 0.f ? -r : r;
}

__global__ void __launch_bounds__(HID, 1) rnn_kernel(
    const float* __restrict__ x,        // [B, T, 1]
    const float* __restrict__ W_embed,  // [H, 1]
    const float* __restrict__ b_embed,  // [H]
    const float* __restrict__ b_update, // [H]
    const float* __restrict__ gamma,    // [H]
    const float* __restrict__ beta,     // [H]
    const float* __restrict__ W_out,    // [10, H]
    const float* __restrict__ b_out,    // [10]
    const float* __restrict__ csp,      // scalar
    float* __restrict__ out)            // [B, 10]
{
    __shared__ __align__(16) float sv[GB][HID];   // combined+h vectors (matvec input)
    __shared__ float2 red[8][GB];                 // per-warp (sum, sumsq) partials

    const int j    = threadIdx.x;       // hidden index owned by this thread
    const int lane = j & 31;
    const int warp = j >> 5;
    const int b0   = blockIdx.x * GB;   // first batch handled by this CTA

    const float cs = 1.f / (1.f + expf(-csp[0]));   // sigmoid(context_strength)
    const float we = W_embed[j];
    const float be = b_embed[j];
    const float bu = b_update[j];
    const float ga = gamma[j];
    const float bt = beta[j];

    float hprev[GB];
    #pragma unroll
    for (int g = 0; g < GB; g++) hprev[g] = 0.f;

    float* mem0 = g_mem + (size_t)b0 * NSLOT * HID;

    for (int t = 0; t < TLEN; t++) {
        // ---- per-step constant weights / slot offsets ----
        float w[5]; int soff[5];
        #pragma unroll
        for (int k = 0; k < 5; k++) {
            w[k]    = g_wtab[t * 8 + k];
            soff[k] = g_itab[t * 8 + k] * HID + j;
        }

        // ---- gather context + embed + combine -> sv (memory slab: L2-only via ldcg) ----
        #pragma unroll
        for (int g = 0; g < GB; g++) {
            const float* mg = mem0 + g * (NSLOT * HID);
            float ctx = 0.f;
            #pragma unroll
            for (int k = 0; k < 5; k++) ctx = fmaf(w[k], __ldcg(mg + soff[k]), ctx);
            float xv  = __ldg(&x[(b0 + g) * TLEN + t]);
            float inp = fast_tanh(fmaf(xv, we, be));
            sv[g][j]  = fmaf(cs, ctx, inp) + hprev[g];
        }
        __syncthreads();

        // ---- matvec: acc_g[j] = b_update[j] + sum_i Wt[i*H+j] * sv[g][i] ----
        float acc0 = bu, acc1 = bu, acc2 = bu, acc3 = bu;
        const float* wt = g_Wt + j;

        #define MV_STEP(LOADW, IBASE) do {                                          \
            float wa = LOADW(wt + (IBASE + 0) * HID);                               \
            float wb = LOADW(wt + (IBASE + 1) * HID);                               \
            float wc = LOADW(wt + (IBASE + 2) * HID);                               \
            float wd = LOADW(wt + (IBASE + 3) * HID);                               \
            float4 v0 = *(const float4*)&sv[0][IBASE];                              \
            float4 v1 = *(const float4*)&sv[1][IBASE];                              \
            float4 v2 = *(const float4*)&sv[2][IBASE];                              \
            float4 v3 = *(const float4*)&sv[3][IBASE];                              \
            acc0 = fmaf(wa, v0.x, fmaf(wb, v0.y, fmaf(wc, v0.z, fmaf(wd, v0.w, acc0)))); \
            acc1 = fmaf(wa, v1.x, fmaf(wb, v1.y, fmaf(wc, v1.z, fmaf(wd, v1.w, acc1)))); \
            acc2 = fmaf(wa, v2.x, fmaf(wb, v2.y, fmaf(wc, v2.z, fmaf(wd, v2.w, acc2)))); \
            acc3 = fmaf(wa, v3.x, fmaf(wb, v3.y, fmaf(wc, v3.z, fmaf(wd, v3.w, acc3)))); \
        } while (0)
        #define LDCA_(p) (*(p))

        // First 160 KB of W: default loads (stay L1-resident across steps).
        #pragma unroll 4
        for (int i = 0; i < 160; i += 4) MV_STEP(LDCA_, i);
        // Tail 96 KB: L1-bypass so it doesn't thrash the cached region.
        #pragma unroll 4
        for (int i = 160; i < HID; i += 4) MV_STEP(__ldcg, i);
        #undef MV_STEP
        #undef LDCA_

        float hr[GB] = { fast_tanh(acc0), fast_tanh(acc1),
                         fast_tanh(acc2), fast_tanh(acc3) };

        // ---- layernorm reduction (per g over 256 threads) ----
        #pragma unroll
        for (int g = 0; g < GB; g++) {
            float s = hr[g], q = hr[g] * hr[g];
            #pragma unroll
            for (int off = 16; off > 0; off >>= 1) {
                s += __shfl_xor_sync(0xffffffffu, s, off);
                q += __shfl_xor_sync(0xffffffffu, q, off);
            }
            if (lane == 0) red[warp][g] = make_float2(s, q);
        }
        __syncthreads();

        #pragma unroll
        for (int g = 0; g < GB; g++) {
            float s = 0.f, q = 0.f;
            #pragma unroll
            for (int wi = 0; wi < 8; wi++) { float2 r = red[wi][g]; s += r.x; q += r.y; }
            float mu  = s * (1.f / HID);
            float var = fmaf(q, 1.f / HID, -mu * mu);
            float hn  = fmaf((hr[g] - mu) * rsqrtf(var + LN_EPS), ga, bt);

            // memory[b, idx_k, j] += w_k * h  (column j owned by this thread -> race-free)
            float* mg = mem0 + g * (NSLOT * HID);
            #pragma unroll
            for (int k = 0; k < 5; k++) {
                float* p = mg + soff[k];
                __stcg(p, __ldcg(p) + w[k] * hn);
            }
            hprev[g] = hn;
        }
        // next iteration's sv-write / red-write ordering is protected by the
        // __syncthreads() that follows the sv writes at the top of the loop
    }

    // ---- output head: out[b, o] = h . W_out[o,:] + b_out[o] ----
    #pragma unroll
    for (int g = 0; g < GB; g++) sv[g][j] = hprev[g];
    __syncthreads();

    for (int p = warp; p < GB * 10; p += 8) {
        int g = p / 10, o = p % 10;
        float s = 0.f;
        #pragma unroll
        for (int i = lane; i < HID; i += 32)
            s += sv[g][i] * W_out[o * HID + i];
        #pragma unroll
        for (int off = 16; off > 0; off >>= 1)
            s += __shfl_xor_sync(0xffffffffu, s, off);
        if (lane == 0) out[(b0 + g) * 10 + o] = s + b_out[o];
    }
}

extern "C" void kernel_launch(void* const* d_in, const int* in_sizes, int n_in,
                              void* d_out, int out_size) {
    const float* x   = (const float*)d_in[0];  // [512,256,1]
    const float* W_e = (const float*)d_in[1];  // [256,1]
    const float* b_e = (const float*)d_in[2];  // [256]
    const float* W_u = (const float*)d_in[3];  // [256,256]
    const float* b_u = (const float*)d_in[4];  // [256]
    const float* gam = (const float*)d_in[5];  // [256]
    const float* bet = (const float*)d_in[6];  // [256]
    const float* W_o = (const float*)d_in[7];  // [10,256]
    const float* b_o = (const float*)d_in[8];  // [10]
    const float* csp = (const float*)d_in[9];  // scalar
    float* out = (float*)d_out;                // [512,10] float32

    (void)in_sizes; (void)n_in; (void)out_size;

    zero_mem_kernel<<<2048, 1024>>>();
    prep_kernel<<<HID, HID>>>(W_u);
    rnn_kernel<<<NCTA, HID>>>(x, W_e, b_e, b_u, gam, bet, W_o, b_o, csp, out);
}